// round 7
// baseline (speedup 1.0000x reference)
#include <cuda_runtime.h>
#include <cstddef>

typedef unsigned long long u64;

// Scratch (static __device__ — no allocations allowed).
__device__ float g_S[1966080];    // softmaxed weights, all 4 layers
__device__ float g_hA[2097152];   // 512*256*16 (layer1 out, reused by layer3 out)
__device__ float g_hB[1048576];   // 512*128*16 (layer2 out, reused by layer4 out)

// ---------------- packed f32x2 helpers (dual-fp32 pipe) --------------------
__device__ __forceinline__ void fma2(u64& d, u64 a, u64 b) {
    asm("fma.rn.f32x2 %0, %1, %2, %0;" : "+l"(d) : "l"(a), "l"(b));
}
__device__ __forceinline__ u64 mul2(u64 a, u64 b) {
    u64 d; asm("mul.rn.f32x2 %0, %1, %2;" : "=l"(d) : "l"(a), "l"(b)); return d;
}
__device__ __forceinline__ u64 pack2(float x) {
    u64 d; asm("mov.b64 %0, {%1, %1};" : "=l"(d) : "f"(x)); return d;
}
__device__ __forceinline__ u64 packpair(float x, float y) {
    u64 d; asm("mov.b64 %0, {%1, %2};" : "=l"(d) : "f"(x), "f"(y)); return d;
}
__device__ __forceinline__ void unpack2(u64 a, float& lo, float& hi) {
    asm("mov.b64 {%0, %1}, %2;" : "=f"(lo), "=f"(hi) : "l"(a));
}

// ---------------------------------------------------------------------------
// Kernel 1: weight softmax. One block per f-slice (480 blocks, 256 threads).
// ---------------------------------------------------------------------------
__global__ void __launch_bounds__(256) wsoftmax_kernel(
    const float* __restrict__ W1, const float* __restrict__ W2,
    const float* __restrict__ W3, const float* __restrict__ W4)
{
    __shared__ float Ssm[4096];
    __shared__ float red[256];
    __shared__ float mxk[16];

    const int bx = blockIdx.x;
    const int t  = threadIdx.x;
    const float* W; float* S; int f;
    if (bx < 256)      { W = W1; S = g_S;           f = bx;       }
    else if (bx < 384) { W = W2; S = g_S + 1048576; f = bx - 256; }
    else if (bx < 448) { W = W3; S = g_S + 1572864; f = bx - 384; }
    else               { W = W4; S = g_S + 1835008; f = bx - 448; }

    const float4* Wg = (const float4*)(W + (size_t)f * 4096);
    float4*       Sg = (float4*)(S + (size_t)f * 4096);

    #pragma unroll
    for (int q = 0; q < 4; q++) ((float4*)Ssm)[t + 256 * q] = Wg[t + 256 * q];
    __syncthreads();

    const int k = t & 15;
    const int g = t >> 4;

    float pm = -1e30f;
    #pragma unroll
    for (int mm = 0; mm < 16; mm++) pm = fmaxf(pm, Ssm[(g * 16 + mm) * 16 + k]);
    red[g * 16 + k] = pm;
    __syncthreads();
    #pragma unroll
    for (int st = 8; st > 0; st >>= 1) {
        if (g < st) red[g * 16 + k] = fmaxf(red[g * 16 + k], red[(g + st) * 16 + k]);
        __syncthreads();
    }
    if (g == 0) mxk[k] = red[k];
    __syncthreads();

    const float mx = mxk[k];
    float ps = 0.f;
    #pragma unroll
    for (int mm = 0; mm < 16; mm++) {
        int idx = (g * 16 + mm) * 16 + k;
        float e = __expf(Ssm[idx] - mx);
        Ssm[idx] = e;
        ps += e;
    }
    __syncthreads();
    red[g * 16 + k] = ps;
    __syncthreads();
    #pragma unroll
    for (int st = 8; st > 0; st >>= 1) {
        if (g < st) red[g * 16 + k] += red[(g + st) * 16 + k];
        __syncthreads();
    }
    const float inv = 1.f / red[k];
    #pragma unroll
    for (int mm = 0; mm < 16; mm++) Ssm[(g * 16 + mm) * 16 + k] *= inv;
    __syncthreads();

    #pragma unroll
    for (int q = 0; q < 4; q++) Sg[t + 256 * q] = ((float4*)Ssm)[t + 256 * q];
}

// ---------------------------------------------------------------------------
// Kernel 2: one SPN layer. NT=2 samples/thread, KS-way k-split, 128 threads.
//   DUP=true (KS>=2): S staged DUPLICATED in smem ({s,s} pairs, 32KB) so the
//   f32x2 lanes carry (sample0, sample1):
//     A2[i] = {a0[i], a1[i]} (regs), B2[j] = {b0[j], b1[j]} (LDS.64),
//     p2 = mul2(A2, B2)  — ONE instr builds both multipliers, 4-cyc chain —
//     fma2(accd[u], p2, {s,s}).
//   Per (i,j): KO/2 dup-LDS + 1 mul2 + KO fma2 (KS=4: 7 instr vs 9 before;
//   KS=8: 4 vs 7). Bank-exact: s-lanes offset 2*KO*s floats -> disjoint
//   banks; n-lanes broadcast. All grids 512 blocks = single wave.
//   KS=1 keeps the plain path (dup would add LDS there).
// ---------------------------------------------------------------------------
template<int KS, bool DUP>
__global__ void __launch_bounds__(128) layer_kernel(
    const float* __restrict__ hin, const float* __restrict__ Sall,
    float* __restrict__ hout, int F_in, int s_off)
{
    constexpr int KO   = 16 / KS;
    constexpr int NSL  = 128 / KS;
    extern __shared__ float sm[];
    float* Ssm   = sm;                              // 4096 or 8192 floats
    float* Brows = sm + (DUP ? 8192 : 4096);        // NSL rows of 34

    const int tid = threadIdx.x;
    const int s   = tid % KS;
    const int nl  = tid / KS;
    const int f   = blockIdx.x;
    const int F_out = F_in >> 1;
    const int n0 = blockIdx.y * (2 * NSL) + nl;
    const int n1 = n0 + NSL;

    // Stage S_f (coalesced); DUP writes each value twice ({s,s} pairs).
    {
        const float4* Sg = (const float4*)(Sall + (size_t)s_off + (size_t)f * 4096);
        #pragma unroll
        for (int q = 0; q < 8; q++) {
            const int idx = tid + 128 * q;
            float4 v = Sg[idx];
            if constexpr (DUP) {
                ((float4*)Ssm)[2 * idx]     = make_float4(v.x, v.x, v.y, v.y);
                ((float4*)Ssm)[2 * idx + 1] = make_float4(v.z, v.z, v.w, v.w);
            } else {
                ((float4*)Ssm)[idx] = v;
            }
        }
    }

    // Prologue: both samples' children -> maxes, exps.
    float a0[16], a1[16];
    float base0, base1;
    float* row = Brows + nl * 34;
    {
        float v[32];
        const float4* hp = (const float4*)(hin + ((size_t)n0 * F_in + 2 * f) * 16);
        #pragma unroll
        for (int q = 0; q < 8; q++) ((float4*)v)[q] = hp[q];
        float l = v[0], r = v[16];
        #pragma unroll
        for (int i = 1; i < 16; i++) { l = fmaxf(l, v[i]); r = fmaxf(r, v[16 + i]); }
        #pragma unroll
        for (int i = 0; i < 16; i++) a0[i] = __expf(v[i] - l);
        if (s == 0) {
            #pragma unroll
            for (int j = 0; j < 16; j++) row[2 * j] = __expf(v[16 + j] - r);
        }
        base0 = l + r;
    }
    {
        float v[32];
        const float4* hp = (const float4*)(hin + ((size_t)n1 * F_in + 2 * f) * 16);
        #pragma unroll
        for (int q = 0; q < 8; q++) ((float4*)v)[q] = hp[q];
        float l = v[0], r = v[16];
        #pragma unroll
        for (int i = 1; i < 16; i++) { l = fmaxf(l, v[i]); r = fmaxf(r, v[16 + i]); }
        #pragma unroll
        for (int i = 0; i < 16; i++) a1[i] = __expf(v[i] - l);
        if (s == 0) {
            #pragma unroll
            for (int j = 0; j < 16; j++) row[2 * j + 1] = __expf(v[16 + j] - r);
        }
        base1 = l + r;
    }
    __syncthreads();

    if constexpr (DUP) {
        // A2[i] = {a0[i], a1[i]}
        u64 A2[16];
        #pragma unroll
        for (int i = 0; i < 16; i++) A2[i] = packpair(a0[i], a1[i]);

        u64 accd[KO];
        #pragma unroll
        for (int u = 0; u < KO; u++) accd[u] = 0ull;

        #pragma unroll 2
        for (int j = 0; j < 16; j++) {
            const u64 B2 = ((const u64*)row)[j];            // {b0j, b1j}
            const float* basep = Ssm + j * 32 + 2 * KO * s; // dup row for m=i*16+j
            #pragma unroll
            for (int i = 0; i < 16; i++) {
                const u64 p2 = mul2(A2[i], B2);
                const u64* q = (const u64*)(basep + i * 512);
                #pragma unroll
                for (int u = 0; u < KO; u++) fma2(accd[u], p2, q[u]);
            }
        }

        float o0[KO], o1[KO];
        #pragma unroll
        for (int u = 0; u < KO; u++) {
            float v0, v1; unpack2(accd[u], v0, v1);
            o0[u] = __logf(v0) + base0;
            o1[u] = __logf(v1) + base1;
        }
        float* op0 = hout + ((size_t)n0 * F_out + f) * 16 + KO * s;
        float* op1 = hout + ((size_t)n1 * F_out + f) * 16 + KO * s;
        if constexpr (KO >= 4) {
            #pragma unroll
            for (int q = 0; q < KO / 4; q++) {
                ((float4*)op0)[q] = ((float4*)o0)[q];
                ((float4*)op1)[q] = ((float4*)o1)[q];
            }
        } else {
            ((float2*)op0)[0] = make_float2(o0[0], o0[1]);
            ((float2*)op1)[0] = make_float2(o1[0], o1[1]);
        }
    } else {
        // KS==1 plain path (k-paired accs).
        u64 acc0[8], acc1[8];
        #pragma unroll
        for (int u = 0; u < 8; u++) { acc0[u] = 0ull; acc1[u] = 0ull; }

        #pragma unroll 2
        for (int j = 0; j < 16; j++) {
            float b0, b1;
            unpack2(((const u64*)row)[j], b0, b1);
            const float* Sj = Ssm + j * 16;
            #pragma unroll
            for (int i = 0; i < 16; i++) {
                const u64* q = (const u64*)(Sj + i * 256);
                const u64 p0 = pack2(a0[i] * b0);
                const u64 p1 = pack2(a1[i] * b1);
                #pragma unroll
                for (int u = 0; u < 8; u++) fma2(acc0[u], p0, q[u]);
                #pragma unroll
                for (int u = 0; u < 8; u++) fma2(acc1[u], p1, q[u]);
            }
        }

        float o0[16], o1[16];
        #pragma unroll
        for (int u = 0; u < 8; u++) {
            float lo, hi;
            unpack2(acc0[u], lo, hi);
            o0[2 * u] = __logf(lo) + base0;  o0[2 * u + 1] = __logf(hi) + base0;
            unpack2(acc1[u], lo, hi);
            o1[2 * u] = __logf(lo) + base1;  o1[2 * u + 1] = __logf(hi) + base1;
        }
        float4* op0 = (float4*)(hout + ((size_t)n0 * F_out + f) * 16);
        float4* op1 = (float4*)(hout + ((size_t)n1 * F_out + f) * 16);
        #pragma unroll
        for (int q = 0; q < 4; q++) {
            op0[q] = ((float4*)o0)[q];
            op1[q] = ((float4*)o1)[q];
        }
    }
}

// ---------------------------------------------------------------------------
// Kernel 3: root. Block per n (512 blocks, 32 threads), warp-shfl reduce.
// ---------------------------------------------------------------------------
__global__ void __launch_bounds__(32) root_kernel(
    const float* __restrict__ h4, const float* __restrict__ Wroot,
    float* __restrict__ out)
{
    const int n = blockIdx.x;
    const int t = threadIdx.x;
    const float4* hp = (const float4*)(h4 + (size_t)n * 512);

    float4 a = make_float4(0.f, 0.f, 0.f, 0.f);
    #pragma unroll
    for (int r = 0; r < 4; r++) {
        float4 q = hp[t + 32 * r];
        a.x += q.x; a.y += q.y; a.z += q.z; a.w += q.w;
    }
    #pragma unroll
    for (int st = 4; st <= 16; st <<= 1) {
        a.x += __shfl_xor_sync(0xffffffffu, a.x, st);
        a.y += __shfl_xor_sync(0xffffffffu, a.y, st);
        a.z += __shfl_xor_sync(0xffffffffu, a.z, st);
        a.w += __shfl_xor_sync(0xffffffffu, a.w, st);
    }
    __shared__ float sred[16];
    if (t < 4) { sred[4*t] = a.x; sred[4*t+1] = a.y; sred[4*t+2] = a.z; sred[4*t+3] = a.w; }
    __syncwarp();

    if (t == 0) {
        float w[16];
        #pragma unroll
        for (int k = 0; k < 16; k++) w[k] = Wroot[k];
        float wm = w[0];
        #pragma unroll
        for (int k = 1; k < 16; k++) wm = fmaxf(wm, w[k]);
        float Z = 0.f;
        #pragma unroll
        for (int k = 0; k < 16; k++) Z += __expf(w[k] - wm);
        const float lz = __logf(Z) + wm;

        float tv[16];
        float tm = -1e30f;
        #pragma unroll
        for (int k = 0; k < 16; k++) {
            tv[k] = sred[k] + w[k] - lz;
            tm = fmaxf(tm, tv[k]);
        }
        float ss = 0.f;
        #pragma unroll
        for (int k = 0; k < 16; k++) ss += __expf(tv[k] - tm);
        out[n] = __logf(ss) + tm;
    }
}

// ---------------------------------------------------------------------------
extern "C" void kernel_launch(void* const* d_in, const int* in_sizes, int n_in,
                              void* d_out, int out_size)
{
    const float* x  = (const float*)d_in[0];
    const float* W1 = (const float*)d_in[1];
    const float* W2 = (const float*)d_in[2];
    const float* W3 = (const float*)d_in[3];
    const float* W4 = (const float*)d_in[4];
    const float* Wr = (const float*)d_in[5];
    float* out = (float*)d_out;

    float *S, *hA, *hB;
    cudaGetSymbolAddress((void**)&S,  g_S);
    cudaGetSymbolAddress((void**)&hA, g_hA);
    cudaGetSymbolAddress((void**)&hB, g_hB);

    wsoftmax_kernel<<<480, 256>>>(W1, W2, W3, W4);

    // smem: nondup = 16KB + NSL*34*4; dup = 32KB + NSL*34*4 (all < 48KB).
    const size_t sm1 = 16384 + 128 * 34 * 4;   // 33792
    const size_t sm2 = 32768 +  64 * 34 * 4;   // 41472
    const size_t sm4 = 32768 +  32 * 34 * 4;   // 37120
    const size_t sm8 = 32768 +  16 * 34 * 4;   // 34944

    // All layers: 512 blocks = one full wave, no tail.
    layer_kernel<1, false><<<dim3(256, 2),  128, sm1>>>(x,  S, hA, 512, 0);
    layer_kernel<2, true ><<<dim3(128, 4),  128, sm2>>>(hA, S, hB, 256, 1048576);
    layer_kernel<4, true ><<<dim3(64, 8),   128, sm4>>>(hB, S, hA, 128, 1572864);
    layer_kernel<8, true ><<<dim3(32, 16),  128, sm8>>>(hA, S, hB, 64,  1835008);

    root_kernel<<<512, 32>>>(hB, Wr, out);
}

// round 8
// speedup vs baseline: 1.2202x; 1.2202x over previous
#include <cuda_runtime.h>
#include <cstddef>

typedef unsigned long long u64;

// Scratch (static __device__ — no allocations allowed).
__device__ float g_S[1966080];    // softmaxed weights, all 4 layers
__device__ float g_hA[2097152];   // 512*256*16 (layer1 out, reused by layer3 out)
__device__ float g_hB[1048576];   // 512*128*16 (layer2 out, reused by layer4 out)

// ---------------- packed f32x2 helpers (dual-fp32 pipe) --------------------
__device__ __forceinline__ void fma2(u64& d, u64 a, u64 b) {
    asm("fma.rn.f32x2 %0, %1, %2, %0;" : "+l"(d) : "l"(a), "l"(b));
}
__device__ __forceinline__ u64 add2(u64 a, u64 b) {
    u64 d; asm("add.rn.f32x2 %0, %1, %2;" : "=l"(d) : "l"(a), "l"(b)); return d;
}
__device__ __forceinline__ u64 pack2(float x) {
    u64 d; asm("mov.b64 %0, {%1, %1};" : "=l"(d) : "f"(x)); return d;
}
__device__ __forceinline__ void unpack2(u64 a, float& lo, float& hi) {
    asm("mov.b64 {%0, %1}, %2;" : "=f"(lo), "=f"(hi) : "l"(a));
}

// ---------------------------------------------------------------------------
// Kernel 1: weight softmax. One block per f-slice (480 blocks, 256 threads).
// ---------------------------------------------------------------------------
__global__ void __launch_bounds__(256) wsoftmax_kernel(
    const float* __restrict__ W1, const float* __restrict__ W2,
    const float* __restrict__ W3, const float* __restrict__ W4)
{
    __shared__ float Ssm[4096];
    __shared__ float red[256];
    __shared__ float mxk[16];

    const int bx = blockIdx.x;
    const int t  = threadIdx.x;
    const float* W; float* S; int f;
    if (bx < 256)      { W = W1; S = g_S;           f = bx;       }
    else if (bx < 384) { W = W2; S = g_S + 1048576; f = bx - 256; }
    else if (bx < 448) { W = W3; S = g_S + 1572864; f = bx - 384; }
    else               { W = W4; S = g_S + 1835008; f = bx - 448; }

    const float4* Wg = (const float4*)(W + (size_t)f * 4096);
    float4*       Sg = (float4*)(S + (size_t)f * 4096);

    #pragma unroll
    for (int q = 0; q < 4; q++) ((float4*)Ssm)[t + 256 * q] = Wg[t + 256 * q];
    __syncthreads();

    const int k = t & 15;
    const int g = t >> 4;

    float pm = -1e30f;
    #pragma unroll
    for (int mm = 0; mm < 16; mm++) pm = fmaxf(pm, Ssm[(g * 16 + mm) * 16 + k]);
    red[g * 16 + k] = pm;
    __syncthreads();
    #pragma unroll
    for (int st = 8; st > 0; st >>= 1) {
        if (g < st) red[g * 16 + k] = fmaxf(red[g * 16 + k], red[(g + st) * 16 + k]);
        __syncthreads();
    }
    if (g == 0) mxk[k] = red[k];
    __syncthreads();

    const float mx = mxk[k];
    float ps = 0.f;
    #pragma unroll
    for (int mm = 0; mm < 16; mm++) {
        int idx = (g * 16 + mm) * 16 + k;
        float e = __expf(Ssm[idx] - mx);
        Ssm[idx] = e;
        ps += e;
    }
    __syncthreads();
    red[g * 16 + k] = ps;
    __syncthreads();
    #pragma unroll
    for (int st = 8; st > 0; st >>= 1) {
        if (g < st) red[g * 16 + k] += red[(g + st) * 16 + k];
        __syncthreads();
    }
    const float inv = 1.f / red[k];
    #pragma unroll
    for (int mm = 0; mm < 16; mm++) Ssm[(g * 16 + mm) * 16 + k] *= inv;
    __syncthreads();

    #pragma unroll
    for (int q = 0; q < 4; q++) Sg[t + 256 * q] = ((float4*)Ssm)[t + 256 * q];
}

// ---------------------------------------------------------------------------
// store one k-quad: log + base, float4 store.
// ---------------------------------------------------------------------------
__device__ __forceinline__ void store_quad(float* dst, u64 lo, u64 hi, float base) {
    float x0, x1, x2, x3;
    unpack2(lo, x0, x1);
    unpack2(hi, x2, x3);
    *(float4*)dst = make_float4(__logf(x0) + base, __logf(x1) + base,
                                __logf(x2) + base, __logf(x3) + base);
}

// ---------------------------------------------------------------------------
// Kernel 2: one SPN layer. m-split over i (MS lanes) with XOR-swizzled S.
//   128 threads = NSL n-slots x MS i-lanes; thread (nl, si) owns samples
//   n0 = base+nl, n1 = n0+NSL, i in [G*si, G*si+G), G = 16/MS, ALL 16 k.
//   S layout: float4 of (m, quad q) stored at m*16 + 4*(q ^ (si(i)&3)):
//   si-lanes read distinct quads of the same row -> disjoint banks, LDS.128,
//   16B aligned; nl-lanes broadcast. acc[2q+t] holds logical quad q^(si&3);
//   shfl-xor reduce uses partner register u^(2r) (compile-time) to stay
//   aligned. Per (i,j): 4 LDS.128 + 2 FMUL + 2 MOV + 16 fma2 at EVERY MS.
//   All grids 512 blocks = one wave.
// ---------------------------------------------------------------------------
template<int MS>
__global__ void __launch_bounds__(128) layer_kernel(
    const float* __restrict__ hin, const float* __restrict__ Sall,
    float* __restrict__ hout, int F_in, int s_off)
{
    constexpr int G   = 16 / MS;               // i-values per thread
    constexpr int NSL = 128 / MS;              // n-slots per block
    constexpr int LG  = (G == 16) ? 4 : (G == 8) ? 3 : (G == 4) ? 2 : 1;
    constexpr int XRM = (MS < 4 ? MS : 4) - 1; // quad-xor mask
    constexpr int UJ  = (MS <= 2) ? 2 : MS;    // j-unroll

    extern __shared__ float sm[];
    float* Ssm   = sm;                          // 4096 floats (swizzled)
    float* Brows = sm + 4096;                   // NSL rows of 34

    const int tid = threadIdx.x;
    const int si  = tid & (MS - 1);
    const int nl  = tid / MS;
    const int f   = blockIdx.x;
    const int F_out = F_in >> 1;
    const int n0 = blockIdx.y * (2 * NSL) + nl;
    const int n1 = n0 + NSL;
    const int xr = si & XRM;

    // Stage S_f with quad swizzle, coalesced global reads.
    {
        const float4* Sg = (const float4*)(Sall + (size_t)s_off + (size_t)f * 4096);
        #pragma unroll
        for (int q8 = 0; q8 < 8; q8++) {
            const int idx = tid + 128 * q8;
            float4 v = Sg[idx];
            if constexpr (MS == 1) {
                ((float4*)Ssm)[idx] = v;
            } else {
                const int m = idx >> 2, k4 = idx & 3;
                const int xi = (m >> (4 + LG)) & XRM;  // si(i) & XRM
                *(float4*)(Ssm + m * 16 + 4 * (k4 ^ xi)) = v;
            }
        }
    }

    // Prologue: each thread globally loads only its slices; maxes via shfl.
    float a0[G], a1[G];
    float base0, base1;
    float* row = Brows + nl * 34;
    {
        float av0[G], bv0[G], av1[G], bv1[G];
        const float* h0 = hin + ((size_t)n0 * F_in + 2 * f) * 16 + G * si;
        const float* h1 = hin + ((size_t)n1 * F_in + 2 * f) * 16 + G * si;
        if constexpr (G >= 4) {
            #pragma unroll
            for (int c = 0; c < G / 4; c++) {
                ((float4*)av0)[c] = *(const float4*)(h0 + 4 * c);
                ((float4*)bv0)[c] = *(const float4*)(h0 + 16 + 4 * c);
                ((float4*)av1)[c] = *(const float4*)(h1 + 4 * c);
                ((float4*)bv1)[c] = *(const float4*)(h1 + 16 + 4 * c);
            }
        } else {
            ((float2*)av0)[0] = *(const float2*)(h0);
            ((float2*)bv0)[0] = *(const float2*)(h0 + 16);
            ((float2*)av1)[0] = *(const float2*)(h1);
            ((float2*)bv1)[0] = *(const float2*)(h1 + 16);
        }
        float l0 = av0[0], r0 = bv0[0], l1 = av1[0], r1 = bv1[0];
        #pragma unroll
        for (int d = 1; d < G; d++) {
            l0 = fmaxf(l0, av0[d]); r0 = fmaxf(r0, bv0[d]);
            l1 = fmaxf(l1, av1[d]); r1 = fmaxf(r1, bv1[d]);
        }
        #pragma unroll
        for (int r = 1; r < MS; r <<= 1) {
            l0 = fmaxf(l0, __shfl_xor_sync(0xffffffffu, l0, r));
            r0 = fmaxf(r0, __shfl_xor_sync(0xffffffffu, r0, r));
            l1 = fmaxf(l1, __shfl_xor_sync(0xffffffffu, l1, r));
            r1 = fmaxf(r1, __shfl_xor_sync(0xffffffffu, r1, r));
        }
        #pragma unroll
        for (int d = 0; d < G; d++) {
            a0[d] = __expf(av0[d] - l0);
            a1[d] = __expf(av1[d] - l1);
            row[2 * (G * si + d)]     = __expf(bv0[d] - r0);
            row[2 * (G * si + d) + 1] = __expf(bv1[d] - r1);
        }
        base0 = l0 + r0;
        base1 = l1 + r1;
    }
    __syncthreads();

    // Mainloop. acc[2q+t] = logical quad (q^xr), halves t (k-pairs).
    u64 acc0[8], acc1[8];
    #pragma unroll
    for (int u = 0; u < 8; u++) { acc0[u] = 0ull; acc1[u] = 0ull; }

    const float* pq0 = Ssm + si * (G * 256) + 4 * (0 ^ xr);
    const float* pq1 = Ssm + si * (G * 256) + 4 * (1 ^ xr);
    const float* pq2 = Ssm + si * (G * 256) + 4 * (2 ^ xr);
    const float* pq3 = Ssm + si * (G * 256) + 4 * (3 ^ xr);
    const u64* rowq = (const u64*)row;

    #pragma unroll UJ
    for (int j = 0; j < 16; j++) {
        float b0, b1;
        unpack2(rowq[j], b0, b1);
        const int jo = j * 16;
        #pragma unroll
        for (int d = 0; d < G; d++) {
            const int o = d * 256 + jo;
            const u64 p0 = pack2(a0[d] * b0);
            const u64 p1 = pack2(a1[d] * b1);
            ulonglong2 w;
            w = *(const ulonglong2*)(pq0 + o);
            fma2(acc0[0], p0, w.x); fma2(acc0[1], p0, w.y);
            fma2(acc1[0], p1, w.x); fma2(acc1[1], p1, w.y);
            w = *(const ulonglong2*)(pq1 + o);
            fma2(acc0[2], p0, w.x); fma2(acc0[3], p0, w.y);
            fma2(acc1[2], p1, w.x); fma2(acc1[3], p1, w.y);
            w = *(const ulonglong2*)(pq2 + o);
            fma2(acc0[4], p0, w.x); fma2(acc0[5], p0, w.y);
            fma2(acc1[4], p1, w.x); fma2(acc1[5], p1, w.y);
            w = *(const ulonglong2*)(pq3 + o);
            fma2(acc0[6], p0, w.x); fma2(acc0[7], p0, w.y);
            fma2(acc1[6], p1, w.x); fma2(acc1[7], p1, w.y);
        }
    }

    // Reduce across si lanes. Round r: partner register u^(2r) (r<4), u (r=4).
    if constexpr (MS >= 2) {
        u64 t0[8], t1[8];
        #pragma unroll
        for (int u = 0; u < 8; u++) {
            t0[u] = __shfl_xor_sync(0xffffffffu, acc0[u ^ 2], 1);
            t1[u] = __shfl_xor_sync(0xffffffffu, acc1[u ^ 2], 1);
        }
        #pragma unroll
        for (int u = 0; u < 8; u++) { acc0[u] = add2(acc0[u], t0[u]); acc1[u] = add2(acc1[u], t1[u]); }
    }
    if constexpr (MS >= 4) {
        u64 t0[8], t1[8];
        #pragma unroll
        for (int u = 0; u < 8; u++) {
            t0[u] = __shfl_xor_sync(0xffffffffu, acc0[u ^ 4], 2);
            t1[u] = __shfl_xor_sync(0xffffffffu, acc1[u ^ 4], 2);
        }
        #pragma unroll
        for (int u = 0; u < 8; u++) { acc0[u] = add2(acc0[u], t0[u]); acc1[u] = add2(acc1[u], t1[u]); }
    }
    if constexpr (MS == 8) {
        u64 t0[8], t1[8];
        #pragma unroll
        for (int u = 0; u < 8; u++) {
            t0[u] = __shfl_xor_sync(0xffffffffu, acc0[u], 4);
            t1[u] = __shfl_xor_sync(0xffffffffu, acc1[u], 4);
        }
        #pragma unroll
        for (int u = 0; u < 8; u++) { acc0[u] = add2(acc0[u], t0[u]); acc1[u] = add2(acc1[u], t1[u]); }
    }

    // Store.
    float* o0p = hout + ((size_t)n0 * F_out + f) * 16;
    float* o1p = hout + ((size_t)n1 * F_out + f) * 16;
    if constexpr (MS == 1) {
        #pragma unroll
        for (int q = 0; q < 4; q++) {
            store_quad(o0p + 4 * q, acc0[2 * q], acc0[2 * q + 1], base0);
            store_quad(o1p + 4 * q, acc1[2 * q], acc1[2 * q + 1], base1);
        }
    } else if constexpr (MS == 2) {
        // lane si: physical quads {si?2:0 -> k=si?12:0, si?3:1 -> k=si?8:4}
        const int ka = si ? 12 : 0, kb = si ? 8 : 4;
        u64 A0 = si ? acc0[4] : acc0[0], A1 = si ? acc0[5] : acc0[1];
        u64 B0 = si ? acc0[6] : acc0[2], B1 = si ? acc0[7] : acc0[3];
        store_quad(o0p + ka, A0, A1, base0);
        store_quad(o0p + kb, B0, B1, base0);
        u64 C0 = si ? acc1[4] : acc1[0], C1 = si ? acc1[5] : acc1[1];
        u64 D0 = si ? acc1[6] : acc1[2], D1 = si ? acc1[7] : acc1[3];
        store_quad(o1p + ka, C0, C1, base1);
        store_quad(o1p + kb, D0, D1, base1);
    } else if constexpr (MS == 4) {
        // physical quad 0 = logical si -> k = 4*si
        store_quad(o0p + 4 * si, acc0[0], acc0[1], base0);
        store_quad(o1p + 4 * si, acc1[0], acc1[1], base1);
    } else { // MS == 8: lanes 0-3 carry distinct logical quads (si&3)
        if (si < 4) {
            store_quad(o0p + 4 * si, acc0[0], acc0[1], base0);
            store_quad(o1p + 4 * si, acc1[0], acc1[1], base1);
        }
    }
}

// ---------------------------------------------------------------------------
// Kernel 3: root. Block per n (512 blocks, 32 threads), warp-shfl reduce.
// ---------------------------------------------------------------------------
__global__ void __launch_bounds__(32) root_kernel(
    const float* __restrict__ h4, const float* __restrict__ Wroot,
    float* __restrict__ out)
{
    const int n = blockIdx.x;
    const int t = threadIdx.x;
    const float4* hp = (const float4*)(h4 + (size_t)n * 512);

    float4 a = make_float4(0.f, 0.f, 0.f, 0.f);
    #pragma unroll
    for (int r = 0; r < 4; r++) {
        float4 q = hp[t + 32 * r];
        a.x += q.x; a.y += q.y; a.z += q.z; a.w += q.w;
    }
    #pragma unroll
    for (int st = 4; st <= 16; st <<= 1) {
        a.x += __shfl_xor_sync(0xffffffffu, a.x, st);
        a.y += __shfl_xor_sync(0xffffffffu, a.y, st);
        a.z += __shfl_xor_sync(0xffffffffu, a.z, st);
        a.w += __shfl_xor_sync(0xffffffffu, a.w, st);
    }
    __shared__ float sred[16];
    if (t < 4) { sred[4*t] = a.x; sred[4*t+1] = a.y; sred[4*t+2] = a.z; sred[4*t+3] = a.w; }
    __syncwarp();

    if (t == 0) {
        float w[16];
        #pragma unroll
        for (int k = 0; k < 16; k++) w[k] = Wroot[k];
        float wm = w[0];
        #pragma unroll
        for (int k = 1; k < 16; k++) wm = fmaxf(wm, w[k]);
        float Z = 0.f;
        #pragma unroll
        for (int k = 0; k < 16; k++) Z += __expf(w[k] - wm);
        const float lz = __logf(Z) + wm;

        float tv[16];
        float tm = -1e30f;
        #pragma unroll
        for (int k = 0; k < 16; k++) {
            tv[k] = sred[k] + w[k] - lz;
            tm = fmaxf(tm, tv[k]);
        }
        float ss = 0.f;
        #pragma unroll
        for (int k = 0; k < 16; k++) ss += __expf(tv[k] - tm);
        out[n] = __logf(ss) + tm;
    }
}

// ---------------------------------------------------------------------------
extern "C" void kernel_launch(void* const* d_in, const int* in_sizes, int n_in,
                              void* d_out, int out_size)
{
    const float* x  = (const float*)d_in[0];
    const float* W1 = (const float*)d_in[1];
    const float* W2 = (const float*)d_in[2];
    const float* W3 = (const float*)d_in[3];
    const float* W4 = (const float*)d_in[4];
    const float* Wr = (const float*)d_in[5];
    float* out = (float*)d_out;

    float *S, *hA, *hB;
    cudaGetSymbolAddress((void**)&S,  g_S);
    cudaGetSymbolAddress((void**)&hA, g_hA);
    cudaGetSymbolAddress((void**)&hB, g_hB);

    wsoftmax_kernel<<<480, 256>>>(W1, W2, W3, W4);

    // smem = 16KB (S) + NSL*34*4 (b rows); all grids 512 blocks (one wave).
    const size_t sm1 = 16384 + 128 * 34 * 4;  // 33792
    const size_t sm2 = 16384 +  64 * 34 * 4;  // 25088
    const size_t sm4 = 16384 +  32 * 34 * 4;  // 20736
    const size_t sm8 = 16384 +  16 * 34 * 4;  // 18560

    layer_kernel<1><<<dim3(256, 2),  128, sm1>>>(x,  S, hA, 512, 0);
    layer_kernel<2><<<dim3(128, 4),  128, sm2>>>(hA, S, hB, 256, 1048576);
    layer_kernel<4><<<dim3(64, 8),   128, sm4>>>(hB, S, hA, 128, 1572864);
    layer_kernel<8><<<dim3(32, 16),  128, sm8>>>(hA, S, hB, 64,  1835008);

    root_kernel<<<512, 32>>>(hB, Wr, out);
}